// round 8
// baseline (speedup 1.0000x reference)
#include <cuda_runtime.h>
#include <math.h>

#define E    384
#define EE   (E * E)           // 147456 columns
#define TC   32                // columns per block (one warp-width)
#define NBLK (EE / TC)         // 4608 blocks
#define RG   16                // row groups (= warps per block)
#define KPT  (E / RG)          // 24 rows per thread
#define THREADS (TC * RG)      // 512

// Order-preserving uint staging for per-row max of (t - lse).
// Zero at module load; gm_fin re-zeros after each read (graph-replay safe).
__device__ unsigned g_stage[E];

__device__ __forceinline__ unsigned fkey(float f) {
    unsigned u = __float_as_uint(f);
    return (u & 0x80000000u) ? ~u : (u | 0x80000000u);
}
__device__ __forceinline__ float funkey(unsigned k) {
    return __uint_as_float((k & 0x80000000u) ? (k ^ 0x80000000u) : ~k);
}

__global__ void __launch_bounds__(THREADS, 3)
gm_main(const float* __restrict__ x,
        const float* __restrict__ kern,
        const float* __restrict__ bias,
        const float* __restrict__ space)
{
    __shared__ float x_s[E];
    __shared__ float red[RG][TC];            // cross-warp column-sum reduction
    __shared__ float lse_s[TC];              // per-column logsumexp
    __shared__ float tr[RG][KPT][TC + 1];    // warp-private transpose tiles

    const int tid = threadIdx.x;
    const int cid = tid & 31;       // lane = column within tile
    const int rg  = tid >> 5;       // warp = row group
    const int k0  = rg * KPT;

    const int c = blockIdx.x * TC + cid;   // global column
    const int l = c % E;                   // kron diag index
    const int j = c / E;

    if (tid < E) x_s[tid] = x[tid];
    __syncthreads();

    const float INV_SQRT2 = 0.70710678118654752440f;
    // Diagonal kernel term: only live where row k == l; owned by one warp.
    float dval = 0.0f;
    if (l >= k0 && l < k0 + KPT)
        dval = kern[(size_t)l * EE + c] * x_s[j] * INV_SQRT2;

    // Pass A: stream space+bias, stage t straight into the smem transpose
    // tile (no register array -> low regs -> 3 blocks/SM), accumulate
    // exp-sum. |t| <= ~1 for this layer, so no max-shift is needed.
    float s_local = 0.0f;
    const size_t base = (size_t)k0 * EE + (size_t)c;
    #pragma unroll
    for (int kk = 0; kk < KPT; ++kk) {
        const int k = k0 + kk;
        const size_t idx = base + (size_t)kk * EE;
        float t = space[idx] + bias[idx];
        if (k == l) t += dval;
        t *= x_s[k];
        tr[rg][kk][cid] = t;
        s_local += __expf(t);
    }

    // Column exp-sum across the 16 row-group warps -> logsumexp.
    red[rg][cid] = s_local;
    __syncthreads();
    if (rg == 0) {
        float s_c = red[0][cid];
        #pragma unroll
        for (int r = 1; r < RG; ++r) s_c += red[r][cid];
        lse_s[cid] = __logf(s_c);
    }
    __syncthreads();

    // Pass C: lanes 0..23 of each warp take the max of one row across the
    // 32 columns (stride-33 LDS: conflict-free; lse_s[cc] is a broadcast).
    if (cid < KPT) {
        float best = -INFINITY;
        #pragma unroll
        for (int cc = 0; cc < TC; ++cc)
            best = fmaxf(best, tr[rg][cid][cc] - lse_s[cc]);
        atomicMax(&g_stage[k0 + cid], fkey(best));   // REDG, spread addrs
    }
}

// out[k] = exp(max); then re-zero staging for the next graph replay.
__global__ void gm_fin(float* __restrict__ out) {
    const int k = threadIdx.x;
    out[k] = __expf(funkey(g_stage[k]));
    g_stage[k] = 0u;
}

extern "C" void kernel_launch(void* const* d_in, const int* in_sizes, int n_in,
                              void* d_out, int out_size)
{
    const float* x     = (const float*)d_in[0];
    const float* kern  = (const float*)d_in[1];
    const float* bias  = (const float*)d_in[2];
    const float* space = (const float*)d_in[3];
    float* out = (float*)d_out;

    // Ask for max smem carveout so 3 blocks x ~54.4 KB fit per SM.
    cudaFuncSetAttribute(gm_main, cudaFuncAttributePreferredSharedMemoryCarveout, 100);

    gm_main<<<NBLK, THREADS>>>(x, kern, bias, space);
    gm_fin<<<1, E>>>(out);
}

// round 9
// speedup vs baseline: 1.1152x; 1.1152x over previous
#include <cuda_runtime.h>
#include <math.h>

#define E    384
#define EE   (E * E)           // 147456 columns
#define TC   32                // columns per block (one warp-width)
#define NBLK (EE / TC)         // 4608 blocks
#define RG   16                // row groups (= warps per block)
#define KPT  (E / RG)          // 24 rows per thread, register-resident
#define THREADS (TC * RG)      // 512

// Order-preserving uint staging for per-row max of (t - lse).
// Zero at module load; gm_fin re-zeros after each read (graph-replay safe).
__device__ unsigned g_stage[E];

__device__ __forceinline__ unsigned fkey(float f) {
    unsigned u = __float_as_uint(f);
    return (u & 0x80000000u) ? ~u : (u | 0x80000000u);
}
__device__ __forceinline__ float funkey(unsigned k) {
    return __uint_as_float((k & 0x80000000u) ? (k ^ 0x80000000u) : ~k);
}

__global__ void __launch_bounds__(THREADS, 2)
gm_main(const float* __restrict__ x,
        const float* __restrict__ kern,
        const float* __restrict__ bias,
        const float* __restrict__ space)
{
    __shared__ float red[RG][TC];            // cross-warp column-sum reduction
    __shared__ float tr[RG][KPT][TC + 1];    // warp-private transpose tiles

    const int tid = threadIdx.x;
    const int cid = tid & 31;       // lane = column within tile
    const int rg  = tid >> 5;       // warp = row group
    const int k0  = rg * KPT;

    const int c = blockIdx.x * TC + cid;   // global column
    const int l = c % E;                   // kron diag index
    const int j = c / E;

    const float INV_SQRT2 = 0.70710678118654752440f;
    // Diagonal kernel term: only live where row k == l; owned by one warp.
    // x is tiny and L1/L2-resident: no smem staging, no startup barrier.
    float dval = 0.0f;
    if (l >= k0 && l < k0 + KPT)
        dval = kern[(unsigned)l * (unsigned)EE + (unsigned)c]
               * __ldg(&x[j]) * INV_SQRT2;

    // Pass A: stream space+bias, build t in registers, accumulate exp-sum.
    // |t| <= ~1 for this layer's scaling, so no max-shift is needed.
    float v[KPT];
    float s_local = 0.0f;
    const unsigned base = (unsigned)k0 * (unsigned)EE + (unsigned)c;
    #pragma unroll
    for (int kk = 0; kk < KPT; ++kk) {
        const int k = k0 + kk;
        const unsigned idx = base + (unsigned)kk * (unsigned)EE;
        float t = space[idx] + bias[idx];
        if (k == l) t += dval;
        t *= __ldg(&x[k]);                  // warp-broadcast L1 hit
        v[kk] = t;
        s_local += __expf(t);
    }

    // Column exp-sum across the 16 row-group warps -> logsumexp.
    red[rg][cid] = s_local;
    __syncthreads();
    float s_c = red[0][cid];
    #pragma unroll
    for (int r = 1; r < RG; ++r) s_c += red[r][cid];
    const float lse = __logf(s_c);

    // Pass C (warp-local): transpose (t - lse) through smem, then
    // lanes 0..23 each take the max of one row across 32 columns.
    #pragma unroll
    for (int kk = 0; kk < KPT; ++kk)
        tr[rg][kk][cid] = v[kk] - lse;
    __syncwarp();
    if (cid < KPT) {
        float best = tr[rg][cid][0];
        #pragma unroll
        for (int cc = 1; cc < TC; ++cc)
            best = fmaxf(best, tr[rg][cid][cc]);
        atomicMax(&g_stage[k0 + cid], fkey(best));   // REDG, spread addrs
    }
}

// out[k] = exp(max); then re-zero staging for the next graph replay.
__global__ void gm_fin(float* __restrict__ out) {
    const int k = threadIdx.x;
    out[k] = __expf(funkey(g_stage[k]));
    g_stage[k] = 0u;
}

extern "C" void kernel_launch(void* const* d_in, const int* in_sizes, int n_in,
                              void* d_out, int out_size)
{
    const float* x     = (const float*)d_in[0];
    const float* kern  = (const float*)d_in[1];
    const float* bias  = (const float*)d_in[2];
    const float* space = (const float*)d_in[3];
    float* out = (float*)d_out;

    gm_main<<<NBLK, THREADS>>>(x, kern, bias, space);
    gm_fin<<<1, E>>>(out);
}